// round 14
// baseline (speedup 1.0000x reference)
#include <cuda_runtime.h>

// ---------------- problem constants ----------------
#define SEQ     256
#define BATCH   128
#define HID     256
#define NLAYERS 12
#define NOUT    10

// scan geometry: 128 blocks = 16 unit-groups x 8 batch-groups, persistent
#define SCAN_THREADS 256
#define BB           16            // batch rows per block
#define UB           16            // hidden units per block (=> 64 gate cols)
#define NSYNC        16            // blocks per barrier group (one per by)
#define APITCH       260           // x/h tile row pitch (floats, 16B-aligned rows)
#define TSTRIDE      1056          // partial tile stride: 4 gates * 256 + 32 pad

// smem layout (float offsets)
#define SM_W    0                          // fused W|U slice [512][64]
#define SM_X    (SM_W + 512*64)            // x tile [16][260]
#define SM_H    (SM_X + BB*APITCH)         // h tile [16][260]
#define SM_G    (SM_H + BB*APITCH)         // 16 partial tiles [gate][row][unit]
#define SM_TOT  (SM_G + 16*TSTRIDE)        // 57984 floats = 231936 bytes

typedef unsigned long long ull;

// ---------------- device scratch (no allocations allowed) ----------------
__device__ float    g_seq[2][(size_t)SEQ * BATCH * HID]; // ping-pong layer sequences
__device__ float    g_h[2][BATCH][HID];                  // ping-pong hidden state
__device__ unsigned g_cnt[8][128];                       // per-by barrier counters (512B apart)

// ---------------- packed f32x2 + barrier helpers ----------------
__device__ __forceinline__ ull fma2(ull a, ull b, ull c) {
    ull d;
    asm("fma.rn.f32x2 %0, %1, %2, %3;" : "=l"(d) : "l"(a), "l"(b), "l"(c));
    return d;
}
__device__ __forceinline__ ull pack2(float v) {
    ull d;
    asm("mov.b64 %0, {%1, %1};" : "=l"(d) : "f"(v));
    return d;
}
__device__ __forceinline__ void bar_arrive(unsigned* p) {
    asm volatile("red.release.gpu.add.u32 [%0], %1;" :: "l"(p), "r"(1u) : "memory");
}
__device__ __forceinline__ unsigned ld_acq(const unsigned* p) {
    unsigned v;
    asm volatile("ld.acquire.gpu.u32 %0, [%1];" : "=r"(v) : "l"(p) : "memory");
    return v;
}

// ---------------- math helpers ----------------
__device__ __forceinline__ float sigf(float x) {
    return 1.0f / (1.0f + __expf(-x));
}
__device__ __forceinline__ float tanh_sig(float x) {
    return fmaf(2.0f, sigf(2.0f * x), -1.0f);   // tanh(x) = 2*sigmoid(2x) - 1
}

// ---------------- init: reset barrier counters (deterministic per replay) ----------------
__global__ void init_state_kernel() {
    int i = threadIdx.x;
    if (i < 8) g_cnt[i][0] = 0u;
}

// ---------------- embedding gather -> g_seq[0] laid out [s][b][e] ----------------
__global__ void embed_kernel(const int* __restrict__ x, const float* __restrict__ tab) {
    int idx = blockIdx.x * blockDim.x + threadIdx.x;     // over S*B*64 float4 chunks
    if (idx >= BATCH * SEQ * (HID / 4)) return;
    int e4 = idx & 63;
    int sb = idx >> 6;            // s*BATCH + b
    int b  = sb & (BATCH - 1);
    int s  = sb >> 7;
    int tok = x[b * SEQ + s];
    float4 v = *(const float4*)(tab + (size_t)tok * HID + e4 * 4);
    *(float4*)(&g_seq[0][(size_t)sb * HID + e4 * 4]) = v;
}

// ---------------- cooperative helpers (all 256 threads) ----------------
// Load fused weight slice [512 rows][64 gate cols] for this block's unit group.
__device__ __forceinline__ void load_wslice(float* Wsm, const float* W,
                                            const float* U, int kh0) {
    for (int idx = threadIdx.x; idx < 512 * 16; idx += SCAN_THREADS) {
        int k = idx >> 4;
        int c = idx & 15;
        int gate = c >> 2;
        int u4   = (c & 3) << 2;
        const float* src = (k < 256) ? (W + (size_t)k * 1024)
                                     : (U + (size_t)(k - 256) * 1024);
        float4 v = *(const float4*)(src + gate * 256 + kh0 + u4);
        *(float4*)(Wsm + k * 64 + gate * 16 + u4) = v;
    }
}

// Stage a 16x256 tile into smem (8 float2 per thread), L1 bypass.
__device__ __forceinline__ void stage_full(float* dst, const float* src) {
    #pragma unroll
    for (int i = 0; i < 8; ++i) {
        int idx = threadIdx.x + i * SCAN_THREADS;   // 0..2047 float2 slots
        int r  = idx >> 7;
        int c2 = idx & 127;
        float2 v = __ldcg(((const float2*)(src + r * HID)) + c2);
        ((float2*)(dst + r * APITCH))[c2] = v;
    }
}

__device__ __forceinline__ void zero_tile(float* dst) {
    #pragma unroll
    for (int i = 0; i < 8; ++i) {
        int idx = threadIdx.x + i * SCAN_THREADS;
        int r  = idx >> 7;
        int c2 = idx & 127;
        ((float2*)(dst + r * APITCH))[c2] = make_float2(0.f, 0.f);
    }
}

// ---------------- K=32 chunk matmul ----------------
// Apane = (x|h tile) + w*32 ; wbase = Wsm + (rowbase + w*32)*64 + 4*cg.
// Lane (rg,cg) owns rows {rg,rg+4,rg+8,rg+12} x col quads {4cg..+3, 32+4cg..+3}.
// Output tile layout: [gate][row][unit] (gate stride 256, row stride 16).
__device__ __forceinline__ void mm32(const float* Apane, const float* wbase,
                                     float* gout, int rg, int cg) {
    const float* ar0 = Apane + (rg     ) * APITCH;
    const float* ar1 = Apane + (rg +  4) * APITCH;
    const float* ar2 = Apane + (rg +  8) * APITCH;
    const float* ar3 = Apane + (rg + 12) * APITCH;
    ull acc[4][4];
    #pragma unroll
    for (int q = 0; q < 4; ++q)
        #pragma unroll
        for (int j = 0; j < 4; ++j)
            acc[q][j] = 0ull;

    #pragma unroll 4
    for (int kk4 = 0; kk4 < 8; ++kk4) {           // K = 32 per warp
        float4 av0 = *(const float4*)(ar0 + kk4 * 4);
        float4 av1 = *(const float4*)(ar1 + kk4 * 4);
        float4 av2 = *(const float4*)(ar2 + kk4 * 4);
        float4 av3 = *(const float4*)(ar3 + kk4 * 4);
        #pragma unroll
        for (int s = 0; s < 4; ++s) {
            const float* wr = wbase + (kk4 * 4 + s) * 64;
            ulonglong2 wA = *(const ulonglong2*)(wr);       // cols 4cg..+3
            ulonglong2 wB = *(const ulonglong2*)(wr + 32);  // cols 32+4cg..+3
            float f0 = (s == 0) ? av0.x : (s == 1) ? av0.y : (s == 2) ? av0.z : av0.w;
            float f1 = (s == 0) ? av1.x : (s == 1) ? av1.y : (s == 2) ? av1.z : av1.w;
            float f2 = (s == 0) ? av2.x : (s == 1) ? av2.y : (s == 2) ? av2.z : av2.w;
            float f3 = (s == 0) ? av3.x : (s == 1) ? av3.y : (s == 2) ? av3.z : av3.w;
            ull v;
            v = pack2(f0);
            acc[0][0] = fma2(v, wA.x, acc[0][0]);
            acc[0][1] = fma2(v, wA.y, acc[0][1]);
            acc[0][2] = fma2(v, wB.x, acc[0][2]);
            acc[0][3] = fma2(v, wB.y, acc[0][3]);
            v = pack2(f1);
            acc[1][0] = fma2(v, wA.x, acc[1][0]);
            acc[1][1] = fma2(v, wA.y, acc[1][1]);
            acc[1][2] = fma2(v, wB.x, acc[1][2]);
            acc[1][3] = fma2(v, wB.y, acc[1][3]);
            v = pack2(f2);
            acc[2][0] = fma2(v, wA.x, acc[2][0]);
            acc[2][1] = fma2(v, wA.y, acc[2][1]);
            acc[2][2] = fma2(v, wB.x, acc[2][2]);
            acc[2][3] = fma2(v, wB.y, acc[2][3]);
            v = pack2(f3);
            acc[3][0] = fma2(v, wA.x, acc[3][0]);
            acc[3][1] = fma2(v, wA.y, acc[3][1]);
            acc[3][2] = fma2(v, wB.x, acc[3][2]);
            acc[3][3] = fma2(v, wB.y, acc[3][3]);
        }
    }

    // cols 4cg..+3 -> gate cg>>2, unit (4cg)&15 ; cols 32+4cg -> gate +2
    const int gbase = (cg >> 2) * 256 + ((4 * cg) & 15);
    #pragma unroll
    for (int q = 0; q < 4; ++q) {
        float* p = gout + gbase + (rg + 4 * q) * 16;
        *(ulonglong2*)(p)       = make_ulonglong2(acc[q][0], acc[q][1]);
        *(ulonglong2*)(p + 512) = make_ulonglong2(acc[q][2], acc[q][3]);
    }
}

// ---------------- persistent 12-layer LSTM scan, uniform dual-issue pipeline ----------------
// Per iteration (l,t)  [entry: gsmX = x_t@W, hsm = h_t, xsm = x_{t+1}]:
//   phase1: prefetch next x into regs (LDG), h-mm32(t) by ALL 8 warps -> gsmH
//   syncA ; gates(t) reads 8 x-tiles + 8 h-tiles ; store h ; syncB
//   tid0 arrive ; [l=0,t=255: reload shared weights + sync]
//   x-mm32(t+1) by ALL 8 warps -> gsmX ; tid0 poll (hidden behind mm)
//   syncC ; commit x regs -> xsm ; stage h_{t+1} -> hsm ; syncD
__global__ void __launch_bounds__(SCAN_THREADS, 1)
scan_all_kernel(const float* __restrict__ W0, const float* __restrict__ U0,
                const float* __restrict__ b0,
                const float* __restrict__ Ws, const float* __restrict__ Us,
                const float* __restrict__ bs)
{
    extern __shared__ float sm[];
    float* Wsm = sm + SM_W;
    float* xsm = sm + SM_X;
    float* hsm = sm + SM_H;
    float* gsm = sm + SM_G;

    const int tid = threadIdx.x;
    const int kh0 = blockIdx.x * UB;   // first hidden unit owned
    const int by  = blockIdx.y;
    const int b0r = by * BB;           // first batch row owned
    unsigned* cnt = &g_cnt[by][0];

    // ---- gate-phase mapping ----
    const int gr = tid >> 4;          // local batch row 0..15
    const int gu = tid & 15;          // local hidden unit 0..15
    const int hb = b0r + gr;
    const int hu = kh0 + gu;
    float creg = 0.0f;                // cell state in a register for all 12 layers
    float bi = b0[hu];
    float bf = b0[256 + hu];
    float bg = b0[512 + hu];
    float bo = b0[768 + hu];

    // ---- matmul mapping: warp w owns K chunk [w*32, w*32+32) of each operand ----
    const int w  = tid >> 5;           // 0..7
    const int ln = tid & 31;
    const int rg = ln >> 3;
    const int cg = ln & 7;
    const float* xpane = xsm + w * 32;
    const float* hpane = hsm + w * 32;
    const float* wbx   = Wsm + (size_t)(w * 32) * 64 + 4 * cg;        // W rows
    const float* wbh   = wbx + 256 * 64;                              // U rows
    float* goutX = gsm + w * TSTRIDE;          // x-partial tiles 0..7
    float* goutH = gsm + (8 + w) * TSTRIDE;    // h-partial tiles 8..15

    const float* xin  = g_seq[0];
    float*       yout = g_seq[1];

    // ---- prologue: weights, x_0, h_0 = 0, x_0@W -> gsmX, then x_1 -> xsm ----
    load_wslice(Wsm, W0, U0, kh0);
    stage_full(xsm, xin + (size_t)b0r * HID);
    zero_tile(hsm);
    __syncthreads();
    mm32(xpane, wbx, goutX, rg, cg);           // x_0 @ W
    __syncthreads();
    stage_full(xsm, xin + (size_t)(BATCH + b0r) * HID);   // x_1 (syncA covers)

    unsigned barn = 0;

    for (int l = 0; l < NLAYERS; ++l) {
        for (int t = 0; t < SEQ; ++t) {
            // ---- phase 1: prefetch next x into regs, then h_t @ U ----
            float2 xr[8];
            {
                const float* xsrc =
                    (t <= SEQ - 3) ? xin + ((size_t)(t + 2) * BATCH + b0r) * HID
                  : (t == SEQ - 2) ? yout + (size_t)b0r * HID               // next layer x_0
                                   : yout + (size_t)(BATCH + b0r) * HID;    // next layer x_1
                #pragma unroll
                for (int i = 0; i < 8; ++i) {
                    int idx = tid + i * SCAN_THREADS;
                    int r   = idx >> 7;
                    int c2  = idx & 127;
                    xr[i] = __ldcg(((const float2*)(xsrc + r * HID)) + c2);
                }
            }
            mm32(hpane, wbh, goutH, rg, cg);
            __syncthreads();   // (A) gsmH + gsmX + xsm ready

            // ---- phase 2: gates + state update (all threads) ----
            {
                float s0 = bi, s1 = bf, s2 = bg, s3 = bo;
                const float* base = gsm + gr * 16 + gu;
                #pragma unroll
                for (int ww = 0; ww < 16; ++ww) {      // 8 x-tiles then 8 h-tiles
                    const float* p = base + ww * TSTRIDE;
                    s0 += p[0];
                    s1 += p[256];
                    s2 += p[512];
                    s3 += p[768];
                }
                float ct = sigf(s1) * creg + sigf(s0) * tanh_sig(s2);
                float hv = sigf(s3) * tanh_sig(ct);
                creg = ct;
                __stcg(&g_h[(t + 1) & 1][hb][hu], hv);           // by-group broadcast (L2)
                yout[((size_t)t * BATCH + hb) * HID + hu] = hv;  // layer output sequence
            }

            if (l == NLAYERS - 1 && t == SEQ - 1) break;

            __syncthreads();   // (B) all h stores issued; gsm reads done
            if (tid == 0) bar_arrive(cnt);
            ++barn;

            if (l == 0 && t == SEQ - 1) {      // one-time switch to shared weights
                load_wslice(Wsm, Ws, Us, kh0);
                __syncthreads();
                bi = bs[hu];
                bf = bs[256 + hu];
                bg = bs[512 + hu];
                bo = bs[768 + hu];
            }

            // ---- phase 3: x-mm for step t+1 (or next layer's x_0); poll hidden ----
            mm32(xpane, wbx, goutX, rg, cg);
            if (tid == 0) {
                const unsigned tgt = barn * NSYNC;
                while (ld_acq(cnt) < tgt) { }          // single poller per block
            }
            __syncthreads();   // (C) xsm consumed; h_{t+1} globally visible

            // commit prefetched x into xsm; stage h_{t+1} into hsm
            #pragma unroll
            for (int i = 0; i < 8; ++i) {
                int idx = tid + i * SCAN_THREADS;
                int r   = idx >> 7;
                int c2  = idx & 127;
                ((float2*)(xsm + r * APITCH))[c2] = xr[i];
            }
            stage_full(hsm, &g_h[(t + 1) & 1][b0r][0]);
            __syncthreads();   // (D) xsm + hsm ready for next iteration
        }
        // swap sequence buffers for next layer
        const float* tx = xin;
        xin  = yout;
        yout = (float*)tx;
    }
}

// ---------------- final FC: one warp per batch row ----------------
__global__ void fc_kernel(const float* __restrict__ fcW,
                          const float* __restrict__ fcb,
                          float* __restrict__ out)
{
    int b  = blockIdx.x;        // 128 blocks
    int ln = threadIdx.x;       // 32 threads
    float acc[NOUT];
    #pragma unroll
    for (int o = 0; o < NOUT; ++o) acc[o] = 0.0f;

    const float* hrow = &g_h[0][b][0];   // t=255 writes parity (255+1)&1 = buf 0
    #pragma unroll
    for (int k = ln; k < HID; k += 32) {
        float hv = __ldcg(hrow + k);
        const float* wr = fcW + k * NOUT;
        #pragma unroll
        for (int o = 0; o < NOUT; ++o)
            acc[o] = fmaf(hv, wr[o], acc[o]);
    }
    #pragma unroll
    for (int off = 16; off > 0; off >>= 1)
        #pragma unroll
        for (int o = 0; o < NOUT; ++o)
            acc[o] += __shfl_down_sync(0xffffffffu, acc[o], off);
    if (ln == 0) {
        #pragma unroll
        for (int o = 0; o < NOUT; ++o)
            out[b * NOUT + o] = acc[o] + fcb[o];
    }
}

// ---------------- launch ----------------
extern "C" void kernel_launch(void* const* d_in, const int* in_sizes, int n_in,
                              void* d_out, int out_size)
{
    const int*   x   = (const int*)  d_in[0];
    const float* tab = (const float*)d_in[1];
    const float* W0  = (const float*)d_in[2];
    const float* U0  = (const float*)d_in[3];
    const float* b0  = (const float*)d_in[4];
    const float* Ws  = (const float*)d_in[5];
    const float* Us  = (const float*)d_in[6];
    const float* bs  = (const float*)d_in[7];
    const float* fcW = (const float*)d_in[8];
    const float* fcb = (const float*)d_in[9];
    float* out = (float*)d_out;

    cudaFuncSetAttribute(scan_all_kernel,
                         cudaFuncAttributeMaxDynamicSharedMemorySize,
                         SM_TOT * (int)sizeof(float));

    init_state_kernel<<<1, 32>>>();     // reset barrier counters per replay

    embed_kernel<<<(BATCH * SEQ * (HID / 4) + 255) / 256, 256>>>(x, tab);

    scan_all_kernel<<<dim3(16, 8), SCAN_THREADS, SM_TOT * (int)sizeof(float)>>>(
        W0, U0, b0, Ws, Us, bs);

    fc_kernel<<<BATCH, 32>>>(fcW, fcb, out);

    (void)in_sizes; (void)n_in; (void)out_size;
}

// round 16
// speedup vs baseline: 1.1666x; 1.1666x over previous
#include <cuda_runtime.h>

// ---------------- problem constants ----------------
#define SEQ     256
#define BATCH   128
#define HID     256
#define NLAYERS 12
#define NOUT    10

// scan geometry: 128 blocks = 16 unit-groups x 8 batch-groups, persistent
#define SCAN_THREADS 256
#define BB           16            // batch rows per block
#define UB           16            // hidden units per block (=> 64 gate cols)
#define NSYNC        16            // blocks per barrier group (one per by)
#define APITCH       260           // x/h tile row pitch (floats, 16B-aligned rows)
#define TSTRIDE      1056          // partial tile stride: 4 gates * 256 + 32 pad

// smem layout (float offsets)
#define SM_W    0                          // fused W|U slice [512][64]
#define SM_X    (SM_W + 512*64)            // x tile [16][260]
#define SM_H    (SM_X + BB*APITCH)         // h tile [16][260]
#define SM_GH   (SM_H + BB*APITCH)         // 4 h-partial tiles [gate][row][unit]
#define SM_GX0  (SM_GH + 4*TSTRIDE)        // 4 x-partial tiles, buffer 0
#define SM_GX1  (SM_GX0 + 4*TSTRIDE)       // 4 x-partial tiles, buffer 1
#define SM_TOT  (SM_GX1 + 4*TSTRIDE)       // 53760 floats = 215040 bytes

typedef unsigned long long ull;

// ---------------- device scratch (no allocations allowed) ----------------
__device__ float    g_seq[2][(size_t)SEQ * BATCH * HID]; // ping-pong layer sequences
__device__ float    g_h[2][BATCH][HID];                  // ping-pong hidden state
__device__ unsigned g_cnt[8][128];                       // per-by barrier counters (512B apart)

// ---------------- packed f32x2 + barrier helpers ----------------
__device__ __forceinline__ ull fma2(ull a, ull b, ull c) {
    ull d;
    asm("fma.rn.f32x2 %0, %1, %2, %3;" : "=l"(d) : "l"(a), "l"(b), "l"(c));
    return d;
}
__device__ __forceinline__ ull pack2(float v) {
    ull d;
    asm("mov.b64 %0, {%1, %1};" : "=l"(d) : "f"(v));
    return d;
}
__device__ __forceinline__ void bar_arrive(unsigned* p) {
    asm volatile("red.release.gpu.add.u32 [%0], %1;" :: "l"(p), "r"(1u) : "memory");
}
__device__ __forceinline__ unsigned ld_acq(const unsigned* p) {
    unsigned v;
    asm volatile("ld.acquire.gpu.u32 %0, [%1];" : "=r"(v) : "l"(p) : "memory");
    return v;
}
__device__ __forceinline__ void bar_named(int id) {       // 128-thread plain barrier
    asm volatile("bar.sync %0, 128;" :: "r"(id) : "memory");
}
// producer/consumer pairs across the two warp halves (count = 256)
__device__ __forceinline__ void barid_arrive(int id) {
    asm volatile("bar.arrive %0, 256;" :: "r"(id) : "memory");
}
__device__ __forceinline__ void barid_sync(int id) {
    asm volatile("bar.sync %0, 256;" :: "r"(id) : "memory");
}

// ---------------- math helpers ----------------
__device__ __forceinline__ float sigf(float x) {
    // MUFU.RCP fast reciprocal (~2 ulp); rel_err margin vs 1e-3 is ~5x
    return __fdividef(1.0f, 1.0f + __expf(-x));
}
__device__ __forceinline__ float tanh_sig(float x) {
    return fmaf(2.0f, sigf(2.0f * x), -1.0f);   // tanh(x) = 2*sigmoid(2x) - 1
}

// ---------------- init: reset barrier counters (deterministic per replay) ----------------
__global__ void init_state_kernel() {
    int i = threadIdx.x;
    if (i < 8) g_cnt[i][0] = 0u;
}

// ---------------- embedding gather -> g_seq[0] laid out [s][b][e] ----------------
__global__ void embed_kernel(const int* __restrict__ x, const float* __restrict__ tab) {
    int idx = blockIdx.x * blockDim.x + threadIdx.x;     // over S*B*64 float4 chunks
    if (idx >= BATCH * SEQ * (HID / 4)) return;
    int e4 = idx & 63;
    int sb = idx >> 6;            // s*BATCH + b
    int b  = sb & (BATCH - 1);
    int s  = sb >> 7;
    int tok = x[b * SEQ + s];
    float4 v = *(const float4*)(tab + (size_t)tok * HID + e4 * 4);
    *(float4*)(&g_seq[0][(size_t)sb * HID + e4 * 4]) = v;
}

// ---------------- cooperative helpers ----------------
// Full-block weight slice load (prologue): fused [512 rows][64 gate cols].
__device__ __forceinline__ void load_wslice(float* Wsm, const float* W,
                                            const float* U, int kh0) {
    for (int idx = threadIdx.x; idx < 512 * 16; idx += SCAN_THREADS) {
        int k = idx >> 4;
        int c = idx & 15;
        int gate = c >> 2;
        int u4   = (c & 3) << 2;
        const float* src = (k < 256) ? (W + (size_t)k * 1024)
                                     : (U + (size_t)(k - 256) * 1024);
        float4 v = *(const float4*)(src + gate * 256 + kh0 + u4);
        *(float4*)(Wsm + k * 64 + gate * 16 + u4) = v;
    }
}

// Half-block weight load: 256 rows from src into Wsm rows [rowbase, rowbase+256).
__device__ __forceinline__ void load_w_half(float* Wsm, const float* src,
                                            int kh0, int rowbase, int ltid) {
    for (int idx = ltid; idx < 256 * 16; idx += 128) {
        int k = idx >> 4;
        int c = idx & 15;
        int gate = c >> 2;
        int u4   = (c & 3) << 2;
        float4 v = *(const float4*)(src + (size_t)k * 1024 + gate * 256 + kh0 + u4);
        *(float4*)(Wsm + (size_t)(rowbase + k) * 64 + gate * 16 + u4) = v;
    }
}

// 128-thread staging of a 16x256 tile (L1 bypass: data produced by other SMs).
__device__ __forceinline__ void stage_half(float* dst, const float* src, int ltid) {
    for (int idx = ltid; idx < BB * (HID / 2); idx += 128) {
        int r  = idx >> 7;
        int c2 = idx & 127;
        float2 v = __ldcg(((const float2*)(src + r * HID)) + c2);
        ((float2*)(dst + r * APITCH))[c2] = v;
    }
}

__device__ __forceinline__ void zero_tile(float* dst) {
    for (int idx = threadIdx.x; idx < BB * (HID / 2); idx += SCAN_THREADS) {
        int r  = idx >> 7;
        int c2 = idx & 127;
        ((float2*)(dst + r * APITCH))[c2] = make_float2(0.f, 0.f);
    }
}

// ---------------- K=64 chunk matmul (accumulation math identical to R12) ----------------
// Lane (rg,cg) owns rows {rg,rg+4,rg+8,rg+12} x col quads {4cg..+3, 32+4cg..+3}.
// Output tile layout: [gate][row][unit] — gate stride 256, row stride 16 —
// so gates-phase reads are tid-contiguous (bank-conflict-free).
__device__ __forceinline__ void mm_chunk(const float* Apane, const float* wbase,
                                         float* gout, int rg, int cg) {
    const float* ar0 = Apane + (rg     ) * APITCH;
    const float* ar1 = Apane + (rg +  4) * APITCH;
    const float* ar2 = Apane + (rg +  8) * APITCH;
    const float* ar3 = Apane + (rg + 12) * APITCH;
    ull acc[4][4];
    #pragma unroll
    for (int q = 0; q < 4; ++q)
        #pragma unroll
        for (int j = 0; j < 4; ++j)
            acc[q][j] = 0ull;

    #pragma unroll 4
    for (int kk4 = 0; kk4 < 16; ++kk4) {
        float4 av0 = *(const float4*)(ar0 + kk4 * 4);
        float4 av1 = *(const float4*)(ar1 + kk4 * 4);
        float4 av2 = *(const float4*)(ar2 + kk4 * 4);
        float4 av3 = *(const float4*)(ar3 + kk4 * 4);
        #pragma unroll
        for (int s = 0; s < 4; ++s) {
            const float* wr = wbase + (kk4 * 4 + s) * 64;
            ulonglong2 wA = *(const ulonglong2*)(wr);       // cols 4cg..+3
            ulonglong2 wB = *(const ulonglong2*)(wr + 32);  // cols 32+4cg..+3
            float f0 = (s == 0) ? av0.x : (s == 1) ? av0.y : (s == 2) ? av0.z : av0.w;
            float f1 = (s == 0) ? av1.x : (s == 1) ? av1.y : (s == 2) ? av1.z : av1.w;
            float f2 = (s == 0) ? av2.x : (s == 1) ? av2.y : (s == 2) ? av2.z : av2.w;
            float f3 = (s == 0) ? av3.x : (s == 1) ? av3.y : (s == 2) ? av3.z : av3.w;
            ull v;
            v = pack2(f0);
            acc[0][0] = fma2(v, wA.x, acc[0][0]);
            acc[0][1] = fma2(v, wA.y, acc[0][1]);
            acc[0][2] = fma2(v, wB.x, acc[0][2]);
            acc[0][3] = fma2(v, wB.y, acc[0][3]);
            v = pack2(f1);
            acc[1][0] = fma2(v, wA.x, acc[1][0]);
            acc[1][1] = fma2(v, wA.y, acc[1][1]);
            acc[1][2] = fma2(v, wB.x, acc[1][2]);
            acc[1][3] = fma2(v, wB.y, acc[1][3]);
            v = pack2(f2);
            acc[2][0] = fma2(v, wA.x, acc[2][0]);
            acc[2][1] = fma2(v, wA.y, acc[2][1]);
            acc[2][2] = fma2(v, wB.x, acc[2][2]);
            acc[2][3] = fma2(v, wB.y, acc[2][3]);
            v = pack2(f3);
            acc[3][0] = fma2(v, wA.x, acc[3][0]);
            acc[3][1] = fma2(v, wA.y, acc[3][1]);
            acc[3][2] = fma2(v, wB.x, acc[3][2]);
            acc[3][3] = fma2(v, wB.y, acc[3][3]);
        }
    }

    // fused col c=4cg: gate c>>4, unit c&15; col c+32: gate +2, same unit
    const int g0 = cg >> 2;              // (4cg)>>4
    const int u0 = (cg & 3) * 4;         // (4cg)&15
    float* p0 = gout + g0 * 256 + u0;
    float* p1 = gout + (g0 + 2) * 256 + u0;
    #pragma unroll
    for (int q = 0; q < 4; ++q) {
        const int roff = (rg + 4 * q) * 16;
        *(ulonglong2*)(p0 + roff) = make_ulonglong2(acc[q][0], acc[q][1]);
        *(ulonglong2*)(p1 + roff) = make_ulonglong2(acc[q][2], acc[q][3]);
    }
}

// ---------------- persistent 12-layer LSTM scan, decoupled warp pipeline ----------------
// EXACT R12 (13.15ms) structure. Per iteration t:
//   phase1: [h-warps: h_t@U -> gsmH | x-warps: stage next x]      __syncthreads (A)
//   gates_t (all threads; reads gsmX[t&1] + gsmH)
//   split:  x-warps bar.arrive(3) -> x_{t+1}@W -> gsmX[(t+1)&1]   (never blocks)
//           h-warps bar.sync(3) -> grid arrive/poll -> stage h_{t+1}
__global__ void __launch_bounds__(SCAN_THREADS, 1)
scan_all_kernel(const float* __restrict__ W0, const float* __restrict__ U0,
                const float* __restrict__ b0,
                const float* __restrict__ Ws, const float* __restrict__ Us,
                const float* __restrict__ bs)
{
    extern __shared__ float sm[];
    float* Wsm   = sm + SM_W;
    float* xsm   = sm + SM_X;
    float* hsm   = sm + SM_H;
    float* gsmH  = sm + SM_GH;
    float* gsmX0 = sm + SM_GX0;
    float* gsmX1 = sm + SM_GX1;

    const int tid = threadIdx.x;
    const int kh0 = blockIdx.x * UB;   // first hidden unit owned
    const int by  = blockIdx.y;
    const int b0r = by * BB;           // first batch row owned
    unsigned* cnt = &g_cnt[by][0];

    // ---- gate-phase mapping ----
    const int gr = tid >> 4;          // local batch row 0..15
    const int gu = tid & 15;          // local hidden unit 0..15
    const int hb = b0r + gr;
    const int hu = kh0 + gu;
    float creg = 0.0f;                // cell state in a register for all 12 layers
    float bi = b0[hu];
    float bf = b0[256 + hu];
    float bg = b0[512 + hu];
    float bo = b0[768 + hu];

    // ---- matmul mapping ----
    const int  w    = tid >> 5;          // 0..7
    const int  ln   = tid & 31;
    const int  rg   = ln >> 3;
    const int  cg   = ln & 7;
    const bool is_x = (w < 4);
    const float* Apane = (is_x ? xsm : hsm) + (w & 3) * 64;   // warp's K chunk
    const float* wbase = Wsm + (size_t)(w * 64) * 64 + 4 * cg;
    float* goutH  = gsmH  + (w & 3) * TSTRIDE;
    float* goutX0 = gsmX0 + (w & 3) * TSTRIDE;
    float* goutX1 = gsmX1 + (w & 3) * TSTRIDE;
    const int ltid = tid & 127;

    const float* xin  = g_seq[0];
    float*       yout = g_seq[1];

    // ---- prologue ----
    load_wslice(Wsm, W0, U0, kh0);
    stage_half(xsm, xin + (size_t)b0r * HID, ltid);   // x_0 (both halves, idempotent)
    zero_tile(hsm);                                    // h_0 = 0
    __syncthreads();
    if (is_x) {
        mm_chunk(Apane, wbase, goutX0, rg, cg);        // x_0@W -> buf0 (gates(0,0))
        bar_named(2);                                  // all x-warps done reading xsm
    }

    unsigned barn = 0;

    for (int l = 0; l < NLAYERS; ++l) {
        for (int t = 0; t < SEQ; ++t) {
            // ---- phase 1: h-warps h_t@U; x-warps stage next x ----
            if (!is_x) {
                mm_chunk(Apane, wbase, goutH, rg, cg);
            } else {
                const float* xsrc = (t < SEQ - 1)
                    ? xin + ((size_t)(t + 1) * BATCH + b0r) * HID   // x_{t+1}
                    : yout + (size_t)b0r * HID;                     // next layer's x_0
                stage_half(xsm, xsrc, ltid);
            }
            __syncthreads();   // (A) gsmX[t&1] (prev split) + gsmH + xsm ready

            // ---- phase 2: gates + state update (all threads) ----
            {
                const float* gx = (t & 1) ? gsmX1 : gsmX0;
                const int goff = gr * 16 + gu;           // == tid: contiguous reads
                float s0 = bi, s1 = bf, s2 = bg, s3 = bo;
                #pragma unroll
                for (int ww = 0; ww < 4; ++ww) {         // x partials (tiles 0-3)
                    const float* p = gx + ww * TSTRIDE + goff;
                    s0 += p[0];
                    s1 += p[256];
                    s2 += p[512];
                    s3 += p[768];
                }
                #pragma unroll
                for (int ww = 0; ww < 4; ++ww) {         // h partials (tiles 0-3)
                    const float* p = gsmH + ww * TSTRIDE + goff;
                    s0 += p[0];
                    s1 += p[256];
                    s2 += p[512];
                    s3 += p[768];
                }
                float ct = sigf(s1) * creg + sigf(s0) * tanh_sig(s2);
                float hv = sigf(s3) * tanh_sig(ct);
                creg = ct;
                __stcg(&g_h[(t + 1) & 1][hb][hu], hv);           // by-group broadcast (L2)
                yout[((size_t)t * BATCH + hb) * HID + hu] = hv;  // layer output sequence
            }

            if (l == NLAYERS - 1 && t == SEQ - 1) break;

            ++barn;
            const unsigned tgt = barn * NSYNC;
            const bool reload = (t == SEQ - 1) && (l == 0);
            if (reload) {                      // switch to shared-layer biases
                bi = bs[hu];
                bf = bs[256 + hu];
                bg = bs[512 + hu];
                bo = bs[768 + hu];
            }

            // ---- phase 3: decoupled split (exactly as R12) ----
            if (is_x) {
                barid_arrive(3);               // non-blocking: signal gates done
                if (reload) {                  // new W half for layers 1..11
                    load_w_half(Wsm, Ws, kh0, 0, ltid);
                    bar_named(2);              // x-warps-only: W visible to all 4
                }
                // x_{t+1}@W into the buffer gates(t+1) will read
                mm_chunk(Apane, wbase, ((t + 1) & 1) ? goutX1 : goutX0, rg, cg);
            } else {
                barid_sync(3);                 // wait x-warps' gates stores
                if (tid == 128) bar_arrive(cnt);        // release block's h stores
                if (reload)                    // new U half (overlaps barrier wait)
                    load_w_half(Wsm, Us, kh0, 256, ltid);
                if (tid == 128) {
                    while (ld_acq(cnt) < tgt) { }       // single poller per block
                }
                bar_named(1);                  // barrier released for all h-warps
                stage_half(hsm, &g_h[(t + 1) & 1][b0r][0], ltid);
                bar_named(1);                  // hsm visible to all h-warps
            }
        }
        // swap sequence buffers for next layer
        const float* tx = xin;
        xin  = yout;
        yout = (float*)tx;
    }
}

// ---------------- final FC: one warp per batch row ----------------
__global__ void fc_kernel(const float* __restrict__ fcW,
                          const float* __restrict__ fcb,
                          float* __restrict__ out)
{
    int b  = blockIdx.x;        // 128 blocks
    int ln = threadIdx.x;       // 32 threads
    float acc[NOUT];
    #pragma unroll
    for (int o = 0; o < NOUT; ++o) acc[o] = 0.0f;

    const float* hrow = &g_h[0][b][0];   // t=255 writes parity (255+1)&1 = buf 0
    #pragma unroll
    for (int k = ln; k < HID; k += 32) {
        float hv = __ldcg(hrow + k);
        const float* wr = fcW + k * NOUT;
        #pragma unroll
        for (int o = 0; o < NOUT; ++o)
            acc[o] = fmaf(hv, wr[o], acc[o]);
    }
    #pragma unroll
    for (int off = 16; off > 0; off >>= 1)
        #pragma unroll
        for (int o = 0; o < NOUT; ++o)
            acc[o] += __shfl_down_sync(0xffffffffu, acc[o], off);
    if (ln == 0) {
        #pragma unroll
        for (int o = 0; o < NOUT; ++o)
            out[b * NOUT + o] = acc[o] + fcb[o];
    }
}

// ---------------- launch ----------------
extern "C" void kernel_launch(void* const* d_in, const int* in_sizes, int n_in,
                              void* d_out, int out_size)
{
    const int*   x   = (const int*)  d_in[0];
    const float* tab = (const float*)d_in[1];
    const float* W0  = (const float*)d_in[2];
    const float* U0  = (const float*)d_in[3];
    const float* b0  = (const float*)d_in[4];
    const float* Ws  = (const float*)d_in[5];
    const float* Us  = (const float*)d_in[6];
    const float* bs  = (const float*)d_in[7];
    const float* fcW = (const float*)d_in[8];
    const float* fcb = (const float*)d_in[9];
    float* out = (float*)d_out;

    cudaFuncSetAttribute(scan_all_kernel,
                         cudaFuncAttributeMaxDynamicSharedMemorySize,
                         SM_TOT * (int)sizeof(float));

    init_state_kernel<<<1, 32>>>();     // reset barrier counters per replay

    embed_kernel<<<(BATCH * SEQ * (HID / 4) + 255) / 256, 256>>>(x, tab);

    scan_all_kernel<<<dim3(16, 8), SCAN_THREADS, SM_TOT * (int)sizeof(float)>>>(
        W0, U0, b0, Ws, Us, bs);

    fc_kernel<<<BATCH, 32>>>(fcW, fcb, out);

    (void)in_sizes; (void)n_in; (void)out_size;
}

// round 17
// speedup vs baseline: 1.1717x; 1.0044x over previous
#include <cuda_runtime.h>

// ---------------- problem constants ----------------
#define SEQ     256
#define BATCH   128
#define HID     256
#define NLAYERS 12
#define NOUT    10

// scan geometry: 128 blocks = 16 unit-groups x 8 batch-groups, persistent
#define SCAN_THREADS 256
#define BB           16            // batch rows per block
#define UB           16            // hidden units per block (=> 64 gate cols)
#define NSYNC        16            // blocks per barrier group (one per by)
#define APITCH       260           // x/h tile row pitch (floats, 16B-aligned rows)
#define TSTRIDE      1056          // partial tile stride: 4 gates * 256 + 32 pad

// smem layout (float offsets)
#define SM_W    0                          // fused W|U slice [512][64]
#define SM_X    (SM_W + 512*64)            // x tile [16][260]
#define SM_H    (SM_X + BB*APITCH)         // h tile [16][260]
#define SM_GH   (SM_H + BB*APITCH)         // 4 h-partial tiles [gate][row][unit]
#define SM_GX0  (SM_GH + 4*TSTRIDE)        // 4 x-partial tiles, buffer 0
#define SM_GX1  (SM_GX0 + 4*TSTRIDE)       // 4 x-partial tiles, buffer 1
#define SM_TOT  (SM_GX1 + 4*TSTRIDE)       // 53760 floats = 215040 bytes

typedef unsigned long long ull;

// ---------------- device scratch (no allocations allowed) ----------------
__device__ float    g_seq[2][(size_t)SEQ * BATCH * HID]; // ping-pong layer sequences
__device__ float    g_h[2][BATCH][HID];                  // ping-pong hidden state
__device__ unsigned g_cnt[8][128];                       // per-by barrier counters (512B apart)

// ---------------- packed f32x2 + barrier helpers ----------------
__device__ __forceinline__ ull fma2(ull a, ull b, ull c) {
    ull d;
    asm("fma.rn.f32x2 %0, %1, %2, %3;" : "=l"(d) : "l"(a), "l"(b), "l"(c));
    return d;
}
__device__ __forceinline__ ull pack2(float v) {
    ull d;
    asm("mov.b64 %0, {%1, %1};" : "=l"(d) : "f"(v));
    return d;
}
__device__ __forceinline__ void bar_arrive(unsigned* p) {
    asm volatile("red.release.gpu.add.u32 [%0], %1;" :: "l"(p), "r"(1u) : "memory");
}
__device__ __forceinline__ unsigned ld_acq(const unsigned* p) {
    unsigned v;
    asm volatile("ld.acquire.gpu.u32 %0, [%1];" : "=r"(v) : "l"(p) : "memory");
    return v;
}
__device__ __forceinline__ void bar_named(int id) {       // 128-thread plain barrier
    asm volatile("bar.sync %0, 128;" :: "r"(id) : "memory");
}
// producer/consumer pair across the two warp halves (count = 256)
__device__ __forceinline__ void barid_arrive(int id) {
    asm volatile("bar.arrive %0, 256;" :: "r"(id) : "memory");
}
__device__ __forceinline__ void barid_sync(int id) {
    asm volatile("bar.sync %0, 256;" :: "r"(id) : "memory");
}

// ---------------- math helpers ----------------
__device__ __forceinline__ float sigf(float x) {
    // MUFU.RCP fast reciprocal (~2 ulp); rel_err margin vs 1e-3 is ~4x
    return __fdividef(1.0f, 1.0f + __expf(-x));
}
__device__ __forceinline__ float tanh_sig(float x) {
    return fmaf(2.0f, sigf(2.0f * x), -1.0f);   // tanh(x) = 2*sigmoid(2x) - 1
}

// ---------------- init: reset barrier counters (deterministic per replay) ----------------
__global__ void init_state_kernel() {
    int i = threadIdx.x;
    if (i < 8) g_cnt[i][0] = 0u;
}

// ---------------- embedding gather -> g_seq[0] laid out [s][b][e] ----------------
__global__ void embed_kernel(const int* __restrict__ x, const float* __restrict__ tab) {
    int idx = blockIdx.x * blockDim.x + threadIdx.x;     // over S*B*64 float4 chunks
    if (idx >= BATCH * SEQ * (HID / 4)) return;
    int e4 = idx & 63;
    int sb = idx >> 6;            // s*BATCH + b
    int b  = sb & (BATCH - 1);
    int s  = sb >> 7;
    int tok = x[b * SEQ + s];
    float4 v = *(const float4*)(tab + (size_t)tok * HID + e4 * 4);
    *(float4*)(&g_seq[0][(size_t)sb * HID + e4 * 4]) = v;
}

// ---------------- cooperative helpers ----------------
// Full-block weight slice load (prologue): fused [512 rows][64 gate cols].
__device__ __forceinline__ void load_wslice(float* Wsm, const float* W,
                                            const float* U, int kh0) {
    for (int idx = threadIdx.x; idx < 512 * 16; idx += SCAN_THREADS) {
        int k = idx >> 4;
        int c = idx & 15;
        int gate = c >> 2;
        int u4   = (c & 3) << 2;
        const float* src = (k < 256) ? (W + (size_t)k * 1024)
                                     : (U + (size_t)(k - 256) * 1024);
        float4 v = *(const float4*)(src + gate * 256 + kh0 + u4);
        *(float4*)(Wsm + k * 64 + gate * 16 + u4) = v;
    }
}

// Half-block weight load: 256 rows from src into Wsm rows [rowbase, rowbase+256).
__device__ __forceinline__ void load_w_half(float* Wsm, const float* src,
                                            int kh0, int rowbase, int ltid) {
    for (int idx = ltid; idx < 256 * 16; idx += 128) {
        int k = idx >> 4;
        int c = idx & 15;
        int gate = c >> 2;
        int u4   = (c & 3) << 2;
        float4 v = *(const float4*)(src + (size_t)k * 1024 + gate * 256 + kh0 + u4);
        *(float4*)(Wsm + (size_t)(rowbase + k) * 64 + gate * 16 + u4) = v;
    }
}

// 128-thread staging of a 16x256 tile (L1 bypass). NOTE: thread ltid always
// writes float2-column (ltid&127) — i.e. warp w writes exactly its own
// 64-float K chunk, so the pattern is column-warp-local by construction.
__device__ __forceinline__ void stage_half(float* dst, const float* src, int ltid) {
    for (int idx = ltid; idx < BB * (HID / 2); idx += 128) {
        int r  = idx >> 7;
        int c2 = idx & 127;
        float2 v = __ldcg(((const float2*)(src + r * HID)) + c2);
        ((float2*)(dst + r * APITCH))[c2] = v;
    }
}

__device__ __forceinline__ void zero_tile(float* dst) {
    for (int idx = threadIdx.x; idx < BB * (HID / 2); idx += SCAN_THREADS) {
        int r  = idx >> 7;
        int c2 = idx & 127;
        ((float2*)(dst + r * APITCH))[c2] = make_float2(0.f, 0.f);
    }
}

// ---------------- K=64 chunk matmul (accumulation math identical to R16) ----------------
// Lane (rg,cg) owns rows {rg,rg+4,rg+8,rg+12} x col quads {4cg..+3, 32+4cg..+3}.
// Output tile layout: [gate][row][unit] — gate stride 256, row stride 16 —
// so gates-phase reads are tid-contiguous (bank-conflict-free).
__device__ __forceinline__ void mm_chunk(const float* Apane, const float* wbase,
                                         float* gout, int rg, int cg) {
    const float* ar0 = Apane + (rg     ) * APITCH;
    const float* ar1 = Apane + (rg +  4) * APITCH;
    const float* ar2 = Apane + (rg +  8) * APITCH;
    const float* ar3 = Apane + (rg + 12) * APITCH;
    ull acc[4][4];
    #pragma unroll
    for (int q = 0; q < 4; ++q)
        #pragma unroll
        for (int j = 0; j < 4; ++j)
            acc[q][j] = 0ull;

    #pragma unroll 4
    for (int kk4 = 0; kk4 < 16; ++kk4) {
        float4 av0 = *(const float4*)(ar0 + kk4 * 4);
        float4 av1 = *(const float4*)(ar1 + kk4 * 4);
        float4 av2 = *(const float4*)(ar2 + kk4 * 4);
        float4 av3 = *(const float4*)(ar3 + kk4 * 4);
        #pragma unroll
        for (int s = 0; s < 4; ++s) {
            const float* wr = wbase + (kk4 * 4 + s) * 64;
            ulonglong2 wA = *(const ulonglong2*)(wr);       // cols 4cg..+3
            ulonglong2 wB = *(const ulonglong2*)(wr + 32);  // cols 32+4cg..+3
            float f0 = (s == 0) ? av0.x : (s == 1) ? av0.y : (s == 2) ? av0.z : av0.w;
            float f1 = (s == 0) ? av1.x : (s == 1) ? av1.y : (s == 2) ? av1.z : av1.w;
            float f2 = (s == 0) ? av2.x : (s == 1) ? av2.y : (s == 2) ? av2.z : av2.w;
            float f3 = (s == 0) ? av3.x : (s == 1) ? av3.y : (s == 2) ? av3.z : av3.w;
            ull v;
            v = pack2(f0);
            acc[0][0] = fma2(v, wA.x, acc[0][0]);
            acc[0][1] = fma2(v, wA.y, acc[0][1]);
            acc[0][2] = fma2(v, wB.x, acc[0][2]);
            acc[0][3] = fma2(v, wB.y, acc[0][3]);
            v = pack2(f1);
            acc[1][0] = fma2(v, wA.x, acc[1][0]);
            acc[1][1] = fma2(v, wA.y, acc[1][1]);
            acc[1][2] = fma2(v, wB.x, acc[1][2]);
            acc[1][3] = fma2(v, wB.y, acc[1][3]);
            v = pack2(f2);
            acc[2][0] = fma2(v, wA.x, acc[2][0]);
            acc[2][1] = fma2(v, wA.y, acc[2][1]);
            acc[2][2] = fma2(v, wB.x, acc[2][2]);
            acc[2][3] = fma2(v, wB.y, acc[2][3]);
            v = pack2(f3);
            acc[3][0] = fma2(v, wA.x, acc[3][0]);
            acc[3][1] = fma2(v, wA.y, acc[3][1]);
            acc[3][2] = fma2(v, wB.x, acc[3][2]);
            acc[3][3] = fma2(v, wB.y, acc[3][3]);
        }
    }

    // fused col c=4cg: gate c>>4, unit c&15; col c+32: gate +2, same unit
    const int g0 = cg >> 2;              // (4cg)>>4
    const int u0 = (cg & 3) * 4;         // (4cg)&15
    float* p0 = gout + g0 * 256 + u0;
    float* p1 = gout + (g0 + 2) * 256 + u0;
    #pragma unroll
    for (int q = 0; q < 4; ++q) {
        const int roff = (rg + 4 * q) * 16;
        *(ulonglong2*)(p0 + roff) = make_ulonglong2(acc[q][0], acc[q][1]);
        *(ulonglong2*)(p1 + roff) = make_ulonglong2(acc[q][2], acc[q][3]);
    }
}

// ---------------- persistent 12-layer LSTM scan, decoupled warp pipeline ----------------
// R16 (12.28ms) structure with the h-path de-serialized:
//   - one grid-counter poller PER H-WARP (lane 0 + __syncwarp) instead of
//     tid128 + 128-thread named barrier
//   - trailing hsm-visibility barrier removed (stage/mm are column-warp-local)
__global__ void __launch_bounds__(SCAN_THREADS, 1)
scan_all_kernel(const float* __restrict__ W0, const float* __restrict__ U0,
                const float* __restrict__ b0,
                const float* __restrict__ Ws, const float* __restrict__ Us,
                const float* __restrict__ bs)
{
    extern __shared__ float sm[];
    float* Wsm   = sm + SM_W;
    float* xsm   = sm + SM_X;
    float* hsm   = sm + SM_H;
    float* gsmH  = sm + SM_GH;
    float* gsmX0 = sm + SM_GX0;
    float* gsmX1 = sm + SM_GX1;

    const int tid = threadIdx.x;
    const int kh0 = blockIdx.x * UB;   // first hidden unit owned
    const int by  = blockIdx.y;
    const int b0r = by * BB;           // first batch row owned
    unsigned* cnt = &g_cnt[by][0];

    // ---- gate-phase mapping ----
    const int gr = tid >> 4;          // local batch row 0..15
    const int gu = tid & 15;          // local hidden unit 0..15
    const int hb = b0r + gr;
    const int hu = kh0 + gu;
    float creg = 0.0f;                // cell state in a register for all 12 layers
    float bi = b0[hu];
    float bf = b0[256 + hu];
    float bg = b0[512 + hu];
    float bo = b0[768 + hu];

    // ---- matmul mapping ----
    const int  w    = tid >> 5;          // 0..7
    const int  ln   = tid & 31;
    const int  rg   = ln >> 3;
    const int  cg   = ln & 7;
    const bool is_x = (w < 4);
    const float* Apane = (is_x ? xsm : hsm) + (w & 3) * 64;   // warp's K chunk
    const float* wbase = Wsm + (size_t)(w * 64) * 64 + 4 * cg;
    float* goutH  = gsmH  + (w & 3) * TSTRIDE;
    float* goutX0 = gsmX0 + (w & 3) * TSTRIDE;
    float* goutX1 = gsmX1 + (w & 3) * TSTRIDE;
    const int ltid = tid & 127;

    const float* xin  = g_seq[0];
    float*       yout = g_seq[1];

    // ---- prologue ----
    load_wslice(Wsm, W0, U0, kh0);
    stage_half(xsm, xin + (size_t)b0r * HID, ltid);   // x_0 (both halves, idempotent)
    zero_tile(hsm);                                    // h_0 = 0
    __syncthreads();
    if (is_x) {
        mm_chunk(Apane, wbase, goutX0, rg, cg);        // x_0@W -> buf0 (gates(0,0))
        __syncwarp();                                  // own-chunk WAR (warp-local)
    }

    unsigned barn = 0;

    for (int l = 0; l < NLAYERS; ++l) {
        for (int t = 0; t < SEQ; ++t) {
            // ---- phase 1: h-warps h_t@U; x-warps stage next x ----
            if (!is_x) {
                mm_chunk(Apane, wbase, goutH, rg, cg);
            } else {
                const float* xsrc = (t < SEQ - 1)
                    ? xin + ((size_t)(t + 1) * BATCH + b0r) * HID   // x_{t+1}
                    : yout + (size_t)b0r * HID;                     // next layer's x_0
                stage_half(xsm, xsrc, ltid);
            }
            __syncthreads();   // (A) gsmX[t&1] (prev split) + gsmH + xsm ready

            // ---- phase 2: gates + state update (all threads) ----
            {
                const float* gx = (t & 1) ? gsmX1 : gsmX0;
                const int goff = gr * 16 + gu;           // == tid: contiguous reads
                float s0 = bi, s1 = bf, s2 = bg, s3 = bo;
                #pragma unroll
                for (int ww = 0; ww < 4; ++ww) {         // x partials (tiles 0-3)
                    const float* p = gx + ww * TSTRIDE + goff;
                    s0 += p[0];
                    s1 += p[256];
                    s2 += p[512];
                    s3 += p[768];
                }
                #pragma unroll
                for (int ww = 0; ww < 4; ++ww) {         // h partials (tiles 0-3)
                    const float* p = gsmH + ww * TSTRIDE + goff;
                    s0 += p[0];
                    s1 += p[256];
                    s2 += p[512];
                    s3 += p[768];
                }
                float ct = sigf(s1) * creg + sigf(s0) * tanh_sig(s2);
                float hv = sigf(s3) * tanh_sig(ct);
                creg = ct;
                __stcg(&g_h[(t + 1) & 1][hb][hu], hv);           // by-group broadcast (L2)
                yout[((size_t)t * BATCH + hb) * HID + hu] = hv;  // layer output sequence
            }

            if (l == NLAYERS - 1 && t == SEQ - 1) break;

            ++barn;
            const unsigned tgt = barn * NSYNC;
            const bool reload = (t == SEQ - 1) && (l == 0);
            if (reload) {                      // switch to shared-layer biases
                bi = bs[hu];
                bf = bs[256 + hu];
                bg = bs[512 + hu];
                bo = bs[768 + hu];
            }

            // ---- phase 3: decoupled split ----
            if (is_x) {
                barid_arrive(3);               // non-blocking: signal gates done
                if (reload) {                  // new W half for layers 1..11
                    load_w_half(Wsm, Ws, kh0, 0, ltid);
                    bar_named(2);              // cross-warp: W rows visible to all 4
                }
                // x_{t+1}@W into the buffer gates(t+1) will read
                mm_chunk(Apane, wbase, ((t + 1) & 1) ? goutX1 : goutX0, rg, cg);
            } else {
                barid_sync(3);                 // x-warps' gates reads of gsmH done
                if (tid == 128) bar_arrive(cnt);        // single release per block
                if (reload)                    // new U half (overlaps barrier wait)
                    load_w_half(Wsm, Us, kh0, 256, ltid);
                if (ln == 0) {
                    while (ld_acq(cnt) < tgt) { }       // ONE poller per h-warp
                }
                __syncwarp();                  // propagate acquire warp-wide
                if (reload) bar_named(1);      // cross-warp: U rows visible (once)
                // stage own hsm chunk (column-warp-local; no trailing barrier)
                stage_half(hsm, &g_h[(t + 1) & 1][b0r][0], ltid);
            }
        }
        // swap sequence buffers for next layer
        const float* tx = xin;
        xin  = yout;
        yout = (float*)tx;
    }
}

// ---------------- final FC: one warp per batch row ----------------
__global__ void fc_kernel(const float* __restrict__ fcW,
                          const float* __restrict__ fcb,
                          float* __restrict__ out)
{
    int b  = blockIdx.x;        // 128 blocks
    int ln = threadIdx.x;       // 32 threads
    float acc[NOUT];
    #pragma unroll
    for (int o = 0; o < NOUT; ++o) acc[o] = 0.0f;

    const float* hrow = &g_h[0][b][0];   // t=255 writes parity (255+1)&1 = buf 0
    #pragma unroll
    for (int k = ln; k < HID; k += 32) {
        float hv = __ldcg(hrow + k);
        const float* wr = fcW + k * NOUT;
        #pragma unroll
        for (int o = 0; o < NOUT; ++o)
            acc[o] = fmaf(hv, wr[o], acc[o]);
    }
    #pragma unroll
    for (int off = 16; off > 0; off >>= 1)
        #pragma unroll
        for (int o = 0; o < NOUT; ++o)
            acc[o] += __shfl_down_sync(0xffffffffu, acc[o], off);
    if (ln == 0) {
        #pragma unroll
        for (int o = 0; o < NOUT; ++o)
            out[b * NOUT + o] = acc[o] + fcb[o];
    }
}

// ---------------- launch ----------------
extern "C" void kernel_launch(void* const* d_in, const int* in_sizes, int n_in,
                              void* d_out, int out_size)
{
    const int*   x   = (const int*)  d_in[0];
    const float* tab = (const float*)d_in[1];
    const float* W0  = (const float*)d_in[2];
    const float* U0  = (const float*)d_in[3];
    const float* b0  = (const float*)d_in[4];
    const float* Ws  = (const float*)d_in[5];
    const float* Us  = (const float*)d_in[6];
    const float* bs  = (const float*)d_in[7];
    const float* fcW = (const float*)d_in[8];
    const float* fcb = (const float*)d_in[9];
    float* out = (float*)d_out;

    cudaFuncSetAttribute(scan_all_kernel,
                         cudaFuncAttributeMaxDynamicSharedMemorySize,
                         SM_TOT * (int)sizeof(float));

    init_state_kernel<<<1, 32>>>();     // reset barrier counters per replay

    embed_kernel<<<(BATCH * SEQ * (HID / 4) + 255) / 256, 256>>>(x, tab);

    scan_all_kernel<<<dim3(16, 8), SCAN_THREADS, SM_TOT * (int)sizeof(float)>>>(
        W0, U0, b0, Ws, Us, bs);

    fc_kernel<<<BATCH, 32>>>(fcW, fcb, out);

    (void)in_sizes; (void)n_in; (void)out_size;
}